// round 1
// baseline (speedup 1.0000x reference)
#include <cuda_runtime.h>
#include <math.h>

#define BS 2
#define NF 8
#define NQ 300
#define HH 96
#define WW 96
#define HW (HH*WW)           // 9216
#define DTOT (NF*HW)         // 73728 per batch

// ---------------- device scratch (no allocations allowed) ----------------
__device__ float g_rowmax[BS*NQ*NF*HH]; // max over w, per (b,q,f,h)  -> src_x
__device__ float g_colmax[BS*NQ*NF*WW]; // max over h, per (b,q,f,w)  -> src_y
__device__ float g_sums  [BS*NQ*NF*3];  // focal, sum(sigmoid), sum(sigmoid*t)
__device__ float g_trm   [BS*NF*WW];    // target max over h, per w  (tgt_y)
__device__ float g_tcm   [BS*NF*HH];    // target max over w, per h  (tgt_x)
__device__ float g_tsum  [BS*NF];       // sum of target mask per (b,f)

// precise-enough sigmoid (fast intrinsics, ~2^-21 rel err)
__device__ __forceinline__ float sigf(float x){
    float e   = __expf(-fabsf(x));
    float inv = __fdividef(1.f, 1.f + e);
    return (x >= 0.f) ? inv : 1.f - inv;
}

// ---------------- kernel A: target reductions ----------------
__global__ void tgt_kernel(const float* __restrict__ tmask){
    int b = blockIdx.x / NF, f = blockIdx.x % NF;
    const float* tm = tmask + (size_t)(b*NF+f)*HW;
    int tid = threadIdx.x;  // 96 threads

    // column maxima (max over h, per w) + sum
    float m = -INFINITY, s = 0.f;
    for (int h = 0; h < HH; h++){
        float v = tm[h*WW + tid];
        m = fmaxf(m, v);
        s += v;
    }
    g_trm[(b*NF+f)*WW + tid] = m;

    // row maxima (max over w, per h)
    float m2 = -INFINITY;
    for (int w = 0; w < WW; w++) m2 = fmaxf(m2, tm[tid*WW + w]);
    g_tcm[(b*NF+f)*HH + tid] = m2;

    // reduce sum over 96 threads (3 warps), deterministic
    __shared__ float sred[3];
    #pragma unroll
    for (int off = 16; off; off >>= 1) s += __shfl_down_sync(0xffffffffu, s, off);
    if ((tid & 31) == 0) sred[tid >> 5] = s;
    __syncthreads();
    if (tid == 0) g_tsum[b*NF+f] = sred[0] + sred[1] + sred[2];
}

// ---------------- kernel B: fused focal/dice/maxima streaming pass ----------------
__global__ __launch_bounds__(288) void main_kernel(
    const float* __restrict__ masks,
    const float* __restrict__ tmask,
    const unsigned char* __restrict__ pad)
{
    int bx  = blockIdx.x;              // b*NQ*NF + q*NF + f
    int b   = bx / (NQ*NF);
    int rem = bx % (NQ*NF);
    int q   = rem / NF;
    int f   = rem % NF;

    const float4* xm = (const float4*)(masks + ((size_t)((b*NF+f)*NQ + q))*HW);
    const float4* tm = (const float4*)(tmask + (size_t)(b*NF+f)*HW);
    const unsigned char* pd = pad + (size_t)b*HW;

    __shared__ float tile[HH*97];      // padded rows: conflict-free row & col scans
    __shared__ float red[9*3];

    int tid = threadIdx.x;
    int fc  = tid % 24;                // float4 column (w block of 4)
    int r0  = tid / 24;                // 0..11

    float focal = 0.f, ssum = 0.f, stsum = 0.f;

    #pragma unroll
    for (int k = 0; k < 8; k++){
        int r = r0 + 12*k;
        float4 x4 = xm[r*24 + fc];
        float4 t4 = tm[r*24 + fc];
        unsigned int pu = *(const unsigned int*)(pd + r*WW + fc*4);
        float xs[4] = {x4.x, x4.y, x4.z, x4.w};
        float ts[4] = {t4.x, t4.y, t4.z, t4.w};
        #pragma unroll
        for (int j = 0; j < 4; j++){
            float x  = ((pu >> (8*j)) & 0xffu) ? 0.f : xs[j];
            float ax = fabsf(x);
            float e  = __expf(-ax);                 // exp(-|x|)
            float inv= __fdividef(1.f, 1.f + e);    // 1/(1+e)
            float p  = (x >= 0.f) ? inv : 1.f - inv;  // sigmoid(x)
            float sp = __logf(1.f + e);             // softplus(-|x|)
            bool  tt = ts[j] > 0.5f;
            float a    = tt ? fmaxf(-x, 0.f) : fmaxf(x, 0.f);
            float qv   = tt ? (1.f - p)      : p;
            float coef = tt ? 0.25f          : 0.75f;
            focal += coef * (a + sp) * qv * qv;     // alpha_t * ce * (1-p_t)^2
            ssum  += p;
            if (tt) stsum += p;
            tile[r*97 + fc*4 + j] = x;
        }
    }

    // deterministic block reduction of the 3 sums
    #pragma unroll
    for (int off = 16; off; off >>= 1){
        focal += __shfl_down_sync(0xffffffffu, focal, off);
        ssum  += __shfl_down_sync(0xffffffffu, ssum,  off);
        stsum += __shfl_down_sync(0xffffffffu, stsum, off);
    }
    int wid = tid >> 5, lane = tid & 31;
    if (lane == 0){ red[wid*3] = focal; red[wid*3+1] = ssum; red[wid*3+2] = stsum; }
    __syncthreads();

    int obase = (b*NQ + q)*NF + f;
    if (tid < 96){
        // row maxima: max over w per h (src_x)
        float m = -INFINITY; int base = tid*97;
        #pragma unroll 8
        for (int w = 0; w < WW; w++) m = fmaxf(m, tile[base + w]);
        g_rowmax[obase*HH + tid] = m;
    } else if (tid < 192){
        // col maxima: max over h per w (src_y)
        int w = tid - 96; float m = -INFINITY;
        #pragma unroll 8
        for (int h = 0; h < HH; h++) m = fmaxf(m, tile[h*97 + w]);
        g_colmax[obase*WW + w] = m;
    } else if (tid < 195){
        int c = tid - 192; float s = 0.f;
        #pragma unroll
        for (int w9 = 0; w9 < 9; w9++) s += red[w9*3 + c];
        g_sums[obase*3 + c] = s;
    }
}

// ---------------- kernel C: assemble cost matrix ----------------
__global__ __launch_bounds__(256) void cost_kernel(
    const float* __restrict__ logits,
    const float* __restrict__ boxes,
    const float* __restrict__ tbox,
    const int*   __restrict__ tvalid,
    float* __restrict__ outC)
{
    int bq = blockIdx.x;
    int b  = bq / NQ;
    int q  = bq % NQ;
    int tid = threadIdx.x;

    float sy=0.f, sty=0.f, tty=0.f, sx=0.f, stx=0.f, ttx=0.f;
    int base = (b*NQ + q)*NF*96;   // 768 per (b,q) — HH==WW==96
    int tb2  = b*NF*96;

    for (int d = tid; d < NF*96; d += 256){
        float smy = sigf(g_colmax[base + d]);
        float ty  = g_trm[tb2 + d];
        sy += smy; sty += smy*ty; tty += ty;
        float smx = sigf(g_rowmax[base + d]);
        float tx  = g_tcm[tb2 + d];
        sx += smx; stx += smx*tx; ttx += tx;
    }

    __shared__ float red[8][6];
    #pragma unroll
    for (int off = 16; off; off >>= 1){
        sy  += __shfl_down_sync(0xffffffffu, sy,  off);
        sty += __shfl_down_sync(0xffffffffu, sty, off);
        tty += __shfl_down_sync(0xffffffffu, tty, off);
        sx  += __shfl_down_sync(0xffffffffu, sx,  off);
        stx += __shfl_down_sync(0xffffffffu, stx, off);
        ttx += __shfl_down_sync(0xffffffffu, ttx, off);
    }
    int wid = tid >> 5, lane = tid & 31;
    if (lane == 0){
        red[wid][0]=sy; red[wid][1]=sty; red[wid][2]=tty;
        red[wid][3]=sx; red[wid][4]=stx; red[wid][5]=ttx;
    }
    __syncthreads();

    if (tid == 0){
        float SY=0,STY=0,TTY=0,SX=0,STX=0,TTX=0;
        for (int w = 0; w < 8; w++){
            SY+=red[w][0]; STY+=red[w][1]; TTY+=red[w][2];
            SX+=red[w][3]; STX+=red[w][4]; TTX+=red[w][5];
        }

        float focal=0.f, S=0.f, ST=0.f, TS=0.f;
        for (int f = 0; f < NF; f++){
            int gb = ((b*NQ + q)*NF + f)*3;
            focal += g_sums[gb];
            S     += g_sums[gb+1];
            ST    += g_sums[gb+2];
            TS    += g_tsum[b*NF + f];
        }
        float cost_mask = focal / (float)DTOT;
        float cost_dice = -(2.f*ST + 1.f) / (S + TS + 1.f);
        float cost_proj = -0.5f * ( (2.f*STY + 1.f)/(SY + TTY + 1.f)
                                  + (2.f*STX + 1.f)/(SX + TTX + 1.f) );

        // class cost (precise math — tiny count)
        float wsum = 0.f, cc = 0.f;
        for (int f = 0; f < NF; f++){
            float wf = (tvalid[b*NF + f] != 0) ? 1.f : 0.f;
            wsum += wf;
            float lg = logits[(b*NF + f)*NQ + q];
            float pp;
            if (lg >= 0.f){ float e = expf(-lg); pp = 1.f/(1.f+e); }
            else          { float e = expf( lg); pp = e/(1.f+e); }
            float pos = 0.25f*(1.f-pp)*(1.f-pp)*(-logf(pp + 1e-8f));
            float neg = 0.75f*pp*pp*(-logf(1.f - pp + 1e-8f));
            cc += (pos - neg)*wf;
        }
        cc /= wsum;

        // bbox + giou
        float bbsum = 0.f, gsum = 0.f;
        for (int f = 0; f < NF; f++){
            const float* sb = boxes + (size_t)((b*NF + f)*NQ + q)*4;
            const float* tb = tbox  + (size_t)(b*NF + f)*4;
            float scx=sb[0], scy=sb[1], sw=sb[2], sh=sb[3];
            float tcx=tb[0], tcy=tb[1], tw=tb[2], th=tb[3];
            bbsum += fabsf(scx-tcx) + fabsf(scy-tcy) + fabsf(sw-tw) + fabsf(sh-th);

            float sx0=scx-0.5f*sw, sy0=scy-0.5f*sh, sx1=scx+0.5f*sw, sy1=scy+0.5f*sh;
            float tx0=tcx-0.5f*tw, ty0=tcy-0.5f*th, tx1=tcx+0.5f*tw, ty1=tcy+0.5f*th;
            float a1=(sx1-sx0)*(sy1-sy0);
            float a2=(tx1-tx0)*(ty1-ty0);
            float ltx=fmaxf(sx0,tx0), lty=fmaxf(sy0,ty0);
            float rbx=fminf(sx1,tx1), rby=fminf(sy1,ty1);
            float iw=fmaxf(rbx-ltx,0.f), ih=fmaxf(rby-lty,0.f);
            float inter=iw*ih;
            float uni=a1+a2-inter;
            float iou=inter/uni;
            float cx0=fminf(sx0,tx0), cy0=fminf(sy0,ty0);
            float cx1=fmaxf(sx1,tx1), cy1=fmaxf(sy1,ty1);
            float cw=fmaxf(cx1-cx0,0.f), ch=fmaxf(cy1-cy0,0.f);
            float ac=cw*ch;
            gsum += iou - (ac-uni)/ac;
        }
        float cost_bbox = bbsum / (float)NF;
        float cost_giou = -gsum / (float)NF;

        outC[b*NQ + q] = cc + cost_bbox + cost_giou + cost_mask + cost_dice + cost_proj;
    }
}

// ---------------- kernel D: argmin + index output ----------------
__global__ __launch_bounds__(512) void argmin_kernel(float* __restrict__ outf, int out_size){
    __shared__ float vmin[16];
    __shared__ int   imin[16];
    int tid = threadIdx.x;
    int wid = tid >> 5, lane = tid & 31;

    for (int b = 0; b < BS; b++){
        float v = (tid < NQ) ? outf[b*NQ + tid] : INFINITY;
        int idx = tid;
        #pragma unroll
        for (int off = 16; off; off >>= 1){
            float v2 = __shfl_down_sync(0xffffffffu, v, off);
            int   i2 = __shfl_down_sync(0xffffffffu, idx, off);
            if (v2 < v || (v2 == v && i2 < idx)){ v = v2; idx = i2; }
        }
        if (lane == 0){ vmin[wid] = v; imin[wid] = idx; }
        __syncthreads();
        if (tid == 0){
            float bv = vmin[0]; int bi = imin[0];
            for (int w = 1; w < 16; w++){
                if (vmin[w] < bv || (vmin[w] == bv && imin[w] < bi)){ bv = vmin[w]; bi = imin[w]; }
            }
            if (out_size == 608){
                long long* ip = (long long*)(outf + BS*NQ);
                ip[b]      = (long long)bi;  // src_ind
                ip[BS + b] = 0LL;            // tgt_ind
            } else if (out_size >= BS*NQ + 2*BS){
                outf[BS*NQ + b]      = (float)bi; // src_ind
                outf[BS*NQ + BS + b] = 0.f;       // tgt_ind
            }
        }
        __syncthreads();
    }
}

// ---------------- launch ----------------
extern "C" void kernel_launch(void* const* d_in, const int* in_sizes, int n_in,
                              void* d_out, int out_size)
{
    const float* logits = (const float*)d_in[0];
    const float* boxes  = (const float*)d_in[1];
    const float* masks  = (const float*)d_in[2];
    const float* tmask  = (const float*)d_in[3];
    const float* tbox   = (const float*)d_in[4];
    const int*   tvalid = (const int*)d_in[5];
    const unsigned char* pad = (const unsigned char*)d_in[6];
    float* outf = (float*)d_out;

    tgt_kernel <<<BS*NF,     96>>>(tmask);
    main_kernel<<<BS*NQ*NF, 288>>>(masks, tmask, pad);
    cost_kernel<<<BS*NQ,    256>>>(logits, boxes, tbox, tvalid, outf);
    argmin_kernel<<<1,      512>>>(outf, out_size);
}

// round 2
// speedup vs baseline: 1.0576x; 1.0576x over previous
#include <cuda_runtime.h>
#include <math.h>

#define BS 2
#define NF 8
#define NQ 300
#define HH 96
#define WW 96
#define HW (HH*WW)           // 9216
#define DTOT (NF*HW)         // 73728 per batch
#define WPR 3                // 3 uint32 words per 96-col row

// ---------------- device scratch (no allocations allowed) ----------------
__device__ unsigned g_tbits[BS*NF*HH*WPR];  // target mask bits, per (b,f): 288 words
__device__ unsigned g_pbits[BS*HH*WPR];     // pad bits, per b: 288 words
__device__ float g_trm  [BS*NF*WW];         // target max over h, per w  (tgt_y)
__device__ float g_tcm  [BS*NF*HH];         // target max over w, per h  (tgt_x)
__device__ float g_tscal[BS*NF*4];          // {tsum, sum(trm), sum(tcm), -}
__device__ float g_rec  [BS*NQ*NF*8];       // {focal, ssum, stsum, sx, stx, sy, sty, -}

// accurate-enough sigmoid (used only on the small 768-element tails)
__device__ __forceinline__ float sigf(float x){
    float e   = __expf(-fabsf(x));
    float inv = __fdividef(1.f, 1.f + e);
    return (x >= 0.f) ? inv : 1.f - inv;
}

__device__ __forceinline__ float tanh_approx(float x){
    float r; asm("tanh.approx.f32 %0, %1;" : "=f"(r) : "f"(x)); return r;
}

// ---------------- kernel A: target reductions + bit packing ----------------
__global__ void tgt_kernel(const float* __restrict__ tmask,
                           const unsigned char* __restrict__ pad){
    int b = blockIdx.x / NF, f = blockIdx.x % NF;
    int bf = b*NF + f;
    const float* tm = tmask + (size_t)bf*HW;
    int tid = threadIdx.x;               // 96 threads
    int lane = tid & 31, wid = tid >> 5; // 3 warps

    // column maxima (max over h, per w) + full sum + bit packing
    float m = -INFINITY, s = 0.f;
    for (int h = 0; h < HH; h++){
        float v = tm[h*WW + tid];
        m = fmaxf(m, v);
        s += v;
        unsigned ball = __ballot_sync(0xffffffffu, v > 0.5f);
        if (lane == 0) g_tbits[bf*HH*WPR + h*WPR + wid] = ball;
    }
    g_trm[bf*WW + tid] = m;

    // row maxima (max over w, per h)
    float m2 = -INFINITY;
    for (int w = 0; w < WW; w++) m2 = fmaxf(m2, tm[tid*WW + w]);
    g_tcm[bf*HH + tid] = m2;

    // pad bit packing (one block-family per b does it)
    if (f == 0){
        const unsigned char* pd = pad + (size_t)b*HW;
        for (int h = 0; h < HH; h++){
            unsigned ball = __ballot_sync(0xffffffffu, pd[h*WW + tid] != 0);
            if (lane == 0) g_pbits[b*HH*WPR + h*WPR + wid] = ball;
        }
    }

    // deterministic reductions of (s, m, m2) over 96 threads
    __shared__ float sred[3][3];
    #pragma unroll
    for (int off = 16; off; off >>= 1){
        s  += __shfl_down_sync(0xffffffffu, s,  off);
        m   = fmaxf(m, m);  // no-op keep
        }
    // redo properly for sums of maxima: sum trm = sum over threads of m, sum tcm = sum of m2
    float sm = m, sm2 = m2;
    #pragma unroll
    for (int off = 16; off; off >>= 1){
        sm  += __shfl_down_sync(0xffffffffu, sm,  off);
        sm2 += __shfl_down_sync(0xffffffffu, sm2, off);
    }
    if (lane == 0){ sred[wid][0] = s; sred[wid][1] = sm; sred[wid][2] = sm2; }
    __syncthreads();
    if (tid == 0){
        g_tscal[bf*4+0] = sred[0][0]+sred[1][0]+sred[2][0];
        g_tscal[bf*4+1] = sred[0][1]+sred[1][1]+sred[2][1];
        g_tscal[bf*4+2] = sred[0][2]+sred[1][2]+sred[2][2];
    }
}

// ---------------- kernel B: fused streaming pass ----------------
__global__ __launch_bounds__(288) void main_kernel(const float* __restrict__ masks)
{
    int bx  = blockIdx.x;              // b*NQ*NF + q*NF + f
    int b   = bx / (NQ*NF);
    int rem = bx % (NQ*NF);
    int q   = rem / NF;
    int f   = rem % NF;
    int bf  = b*NF + f;

    const float4* xm = (const float4*)(masks + ((size_t)(bf*NQ + q))*HW);

    __shared__ float    rowpart[HH*25];    // row-max partials, padded stride 25
    __shared__ float    colpart[12*WW];    // col-max partials per r0 group
    __shared__ unsigned sh_t[HH*WPR];      // 288 target-bit words
    __shared__ unsigned sh_p[HH*WPR];      // 288 pad-bit words
    __shared__ float    red[9*3];
    __shared__ float    red2[6][2];

    int tid = threadIdx.x;
    sh_t[tid] = g_tbits[bf*HH*WPR + tid];
    sh_p[tid] = g_pbits[b *HH*WPR + tid];
    __syncthreads();

    int fc = tid % 24;                 // float4 column (w block of 4)
    int r0 = tid / 24;                 // 0..11
    int wi = fc >> 3;                  // word within row
    int shb = (4*fc) & 31;             // bit offset of column 4*fc

    float cmax0 = -INFINITY, cmax1 = -INFINITY, cmax2 = -INFINITY, cmax3 = -INFINITY;
    float focal = 0.f, ssum = 0.f, stsum = 0.f;

    #pragma unroll
    for (int k = 0; k < 8; k++){
        int r = r0 + 12*k;
        float4 x4 = xm[r*24 + fc];
        unsigned tw = sh_t[r*WPR + wi] >> shb;
        unsigned pw = sh_p[r*WPR + wi] >> shb;
        float rmax = -INFINITY;
        float xs[4] = {x4.x, x4.y, x4.z, x4.w};
        #pragma unroll
        for (int j = 0; j < 4; j++){
            float x = ((pw >> j) & 1u) ? 0.f : xs[j];
            bool tt = (tw >> j) & 1u;
            float th = tanh_approx(0.5f * x);
            float p  = fmaf(0.5f, th, 0.5f);           // sigmoid(x)
            float pt = tt ? p : (1.f - p);             // p_t
            pt = fmaxf(pt, 1e-12f);
            float l  = __logf(pt);                     // -ce
            float qv = 1.f - pt;
            float coef = tt ? -0.25f : -0.75f;
            focal = fmaf(coef * l, qv * qv, focal);    // alpha_t*ce*(1-p_t)^2
            ssum += p;
            if (tt) stsum += p;
            rmax = fmaxf(rmax, x);
            if (j == 0) cmax0 = fmaxf(cmax0, x);
            else if (j == 1) cmax1 = fmaxf(cmax1, x);
            else if (j == 2) cmax2 = fmaxf(cmax2, x);
            else cmax3 = fmaxf(cmax3, x);
        }
        rowpart[r*25 + fc] = rmax;
    }
    ((float4*)colpart)[r0*24 + fc] = make_float4(cmax0, cmax1, cmax2, cmax3);

    // deterministic block reduction of the 3 sums (9 warps)
    #pragma unroll
    for (int off = 16; off; off >>= 1){
        focal += __shfl_down_sync(0xffffffffu, focal, off);
        ssum  += __shfl_down_sync(0xffffffffu, ssum,  off);
        stsum += __shfl_down_sync(0xffffffffu, stsum, off);
    }
    int wid = tid >> 5, lane = tid & 31;
    if (lane == 0){ red[wid*3] = focal; red[wid*3+1] = ssum; red[wid*3+2] = stsum; }
    __syncthreads();

    // tail: projection partial sums
    float a = 0.f, bsum = 0.f;    // (sx,stx) for group A, (sy,sty) for group B
    if (tid < 96){
        int h = tid; float m = -INFINITY;
        #pragma unroll 8
        for (int c = 0; c < 24; c++) m = fmaxf(m, rowpart[h*25 + c]);
        float sp = sigf(m);
        a = sp; bsum = sp * __ldg(&g_tcm[bf*HH + h]);
    } else if (tid < 192){
        int w = tid - 96; float m = -INFINITY;
        #pragma unroll 4
        for (int r = 0; r < 12; r++) m = fmaxf(m, colpart[r*WW + w]);
        float sp = sigf(m);
        a = sp; bsum = sp * __ldg(&g_trm[bf*WW + w]);
    }
    if (tid < 192){
        #pragma unroll
        for (int off = 16; off; off >>= 1){
            a    += __shfl_down_sync(0xffffffffu, a,    off);
            bsum += __shfl_down_sync(0xffffffffu, bsum, off);
        }
        if (lane == 0){ red2[wid][0] = a; red2[wid][1] = bsum; }
    }
    __syncthreads();

    if (tid == 0){
        float F=0,S=0,ST=0;
        #pragma unroll
        for (int w = 0; w < 9; w++){ F += red[w*3]; S += red[w*3+1]; ST += red[w*3+2]; }
        float sx  = red2[0][0]+red2[1][0]+red2[2][0];
        float stx = red2[0][1]+red2[1][1]+red2[2][1];
        float sy  = red2[3][0]+red2[4][0]+red2[5][0];
        float sty = red2[3][1]+red2[4][1]+red2[5][1];
        float* rec = &g_rec[((size_t)(b*NQ + q)*NF + f)*8];
        rec[0]=F; rec[1]=S; rec[2]=ST; rec[3]=sx; rec[4]=stx; rec[5]=sy; rec[6]=sty; rec[7]=0.f;
    }
}

// ---------------- kernel C: assemble cost matrix (1 warp per (b,q)) ----------------
__global__ __launch_bounds__(32) void cost_kernel(
    const float* __restrict__ logits,
    const float* __restrict__ boxes,
    const float* __restrict__ tbox,
    const int*   __restrict__ tvalid,
    float* __restrict__ outC)
{
    int bq = blockIdx.x;
    int b  = bq / NQ;
    int q  = bq % NQ;
    int lane = threadIdx.x;

    float acc[9];
    #pragma unroll
    for (int i = 0; i < 9; i++) acc[i] = 0.f;
    float wsum = 0.f, cc = 0.f, bbsum = 0.f, gsum = 0.f, TS = 0.f, TTY = 0.f, TTX = 0.f;

    if (lane < NF){
        int f = lane, bf = b*NF + f;
        const float* rec = &g_rec[((size_t)(b*NQ + q)*NF + f)*8];
        #pragma unroll
        for (int i = 0; i < 7; i++) acc[i] = rec[i];
        TS  = g_tscal[bf*4+0];
        TTY = g_tscal[bf*4+1];
        TTX = g_tscal[bf*4+2];

        // class cost (precise)
        float wf = (tvalid[bf] != 0) ? 1.f : 0.f;
        wsum = wf;
        float lg = logits[bf*NQ + q];
        float pp;
        if (lg >= 0.f){ float e = expf(-lg); pp = 1.f/(1.f+e); }
        else          { float e = expf( lg); pp = e/(1.f+e); }
        float pos = 0.25f*(1.f-pp)*(1.f-pp)*(-logf(pp + 1e-8f));
        float neg = 0.75f*pp*pp*(-logf(1.f - pp + 1e-8f));
        cc = (pos - neg)*wf;

        // bbox + giou
        const float* sb = boxes + (size_t)(bf*NQ + q)*4;
        const float* tb = tbox  + (size_t)bf*4;
        float scx=sb[0], scy=sb[1], sw=sb[2], sh=sb[3];
        float tcx=tb[0], tcy=tb[1], tw=tb[2], th=tb[3];
        bbsum = fabsf(scx-tcx) + fabsf(scy-tcy) + fabsf(sw-tw) + fabsf(sh-th);

        float sx0=scx-0.5f*sw, sy0=scy-0.5f*sh, sx1=scx+0.5f*sw, sy1=scy+0.5f*sh;
        float tx0=tcx-0.5f*tw, ty0=tcy-0.5f*th, tx1=tcx+0.5f*tw, ty1=tcy+0.5f*th;
        float a1=(sx1-sx0)*(sy1-sy0);
        float a2=(tx1-tx0)*(ty1-ty0);
        float ltx=fmaxf(sx0,tx0), lty=fmaxf(sy0,ty0);
        float rbx=fminf(sx1,tx1), rby=fminf(sy1,ty1);
        float iw=fmaxf(rbx-ltx,0.f), ih=fmaxf(rby-lty,0.f);
        float inter=iw*ih;
        float uni=a1+a2-inter;
        float iou=inter/uni;
        float cx0=fminf(sx0,tx0), cy0=fminf(sy0,ty0);
        float cx1=fmaxf(sx1,tx1), cy1=fmaxf(sy1,ty1);
        float cw=fmaxf(cx1-cx0,0.f), ch=fmaxf(cy1-cy0,0.f);
        float ac=cw*ch;
        gsum = iou - (ac-uni)/ac;
    }

    // reduce over the 8 active lanes
    #pragma unroll
    for (int off = 4; off; off >>= 1){
        #pragma unroll
        for (int i = 0; i < 7; i++) acc[i] += __shfl_down_sync(0xffu, acc[i], off);
        wsum  += __shfl_down_sync(0xffu, wsum,  off);
        cc    += __shfl_down_sync(0xffu, cc,    off);
        bbsum += __shfl_down_sync(0xffu, bbsum, off);
        gsum  += __shfl_down_sync(0xffu, gsum,  off);
        TS    += __shfl_down_sync(0xffu, TS,    off);
        TTY   += __shfl_down_sync(0xffu, TTY,   off);
        TTX   += __shfl_down_sync(0xffu, TTX,   off);
    }

    if (lane == 0){
        float cost_mask = acc[0] / (float)DTOT;
        float cost_dice = -(2.f*acc[2] + 1.f) / (acc[1] + TS + 1.f);
        float cost_proj = -0.5f * ( (2.f*acc[4] + 1.f)/(acc[3] + TTX + 1.f)
                                  + (2.f*acc[6] + 1.f)/(acc[5] + TTY + 1.f) );
        float cost_class = cc / wsum;
        float cost_bbox  = bbsum / (float)NF;
        float cost_giou  = -gsum / (float)NF;
        outC[b*NQ + q] = cost_class + cost_bbox + cost_giou + cost_mask + cost_dice + cost_proj;
    }
}

// ---------------- kernel D: argmin + index output ----------------
__global__ __launch_bounds__(512) void argmin_kernel(float* __restrict__ outf, int out_size){
    __shared__ float vmin[16];
    __shared__ int   imin[16];
    int tid = threadIdx.x;
    int wid = tid >> 5, lane = tid & 31;

    for (int b = 0; b < BS; b++){
        float v = (tid < NQ) ? outf[b*NQ + tid] : INFINITY;
        int idx = tid;
        #pragma unroll
        for (int off = 16; off; off >>= 1){
            float v2 = __shfl_down_sync(0xffffffffu, v, off);
            int   i2 = __shfl_down_sync(0xffffffffu, idx, off);
            if (v2 < v || (v2 == v && i2 < idx)){ v = v2; idx = i2; }
        }
        if (lane == 0){ vmin[wid] = v; imin[wid] = idx; }
        __syncthreads();
        if (tid == 0){
            float bv = vmin[0]; int bi = imin[0];
            for (int w = 1; w < 16; w++){
                if (vmin[w] < bv || (vmin[w] == bv && imin[w] < bi)){ bv = vmin[w]; bi = imin[w]; }
            }
            if (out_size == 608){
                long long* ip = (long long*)(outf + BS*NQ);
                ip[b]      = (long long)bi;  // src_ind
                ip[BS + b] = 0LL;            // tgt_ind
            } else if (out_size >= BS*NQ + 2*BS){
                outf[BS*NQ + b]      = (float)bi; // src_ind
                outf[BS*NQ + BS + b] = 0.f;       // tgt_ind
            }
        }
        __syncthreads();
    }
}

// ---------------- launch ----------------
extern "C" void kernel_launch(void* const* d_in, const int* in_sizes, int n_in,
                              void* d_out, int out_size)
{
    const float* logits = (const float*)d_in[0];
    const float* boxes  = (const float*)d_in[1];
    const float* masks  = (const float*)d_in[2];
    const float* tmask  = (const float*)d_in[3];
    const float* tbox   = (const float*)d_in[4];
    const int*   tvalid = (const int*)d_in[5];
    const unsigned char* pad = (const unsigned char*)d_in[6];
    float* outf = (float*)d_out;

    tgt_kernel <<<BS*NF,     96>>>(tmask, pad);
    main_kernel<<<BS*NQ*NF, 288>>>(masks);
    cost_kernel<<<BS*NQ,     32>>>(logits, boxes, tbox, tvalid, outf);
    argmin_kernel<<<1,      512>>>(outf, out_size);
}